// round 16
// baseline (speedup 1.0000x reference)
#include <cuda_runtime.h>
#include <cuda_fp16.h>
#include <stdint.h>
#include <math.h>

#define D_MODEL 1024
#define HEADS 16
#define DK 64
#define BATCH 2
#define SEQ 2048
#define M_ROWS (BATCH * SEQ)   // 4096
#define BH (BATCH * HEADS)     // 32
#define LOG2E 1.4426950408889634f

typedef __half fp16;

// ---------------- scratch (static device globals; no allocation) -------------
__device__ fp16 g_ahi[(size_t)3 * M_ROWS * D_MODEL];   // activation sets (hi only)
__device__ fp16 g_whi[(size_t)4 * D_MODEL * D_MODEL];  // W^T hi only [N][K]
__device__ fp16 g_qhi[(size_t)BH * SEQ * DK];          // [bh][s][d], pre-scaled 0.125
__device__ fp16 g_khi[(size_t)BH * SEQ * DK];
__device__ fp16 g_vhi[(size_t)BH * DK * SEQ];          // transposed [bh][d][s]

// ---------------------------------------------------------------------------
// MMA building blocks (mma.sync path — tcgen05 unavailable: harness PTX
// targets sm_103 without the 'a' feature suffix). fp16 inputs, fp32 accum.
// ---------------------------------------------------------------------------
#define LDSM4(R0, R1, R2, R3, ADDR) \
    asm volatile("ldmatrix.sync.aligned.m8n8.x4.shared.b16 {%0,%1,%2,%3}, [%4];" \
        : "=r"(R0), "=r"(R1), "=r"(R2), "=r"(R3) : "r"(ADDR))

#define MMA_F16(D, A, B) \
    asm volatile("mma.sync.aligned.m16n8k16.row.col.f32.f16.f16.f32 " \
        "{%0,%1,%2,%3}, {%4,%5,%6,%7}, {%8,%9}, {%0,%1,%2,%3};" \
        : "+f"(D[0]), "+f"(D[1]), "+f"(D[2]), "+f"(D[3]) \
        : "r"(A[0]), "r"(A[1]), "r"(A[2]), "r"(A[3]), "r"(B[0]), "r"(B[1]))

#define CP16(DST, SRC) \
    asm volatile("cp.async.cg.shared.global [%0], [%1], 16;" :: "r"(DST), "l"(SRC))

// ---------------------------------------------------------------------------
// merged converts (grid.z selects tensor) — hi plane only
// ---------------------------------------------------------------------------
struct ConvA { const float* in[3]; fp16* hi[3]; };

__global__ void __launch_bounds__(256) convert_act_kernel(ConvA a)
{
    const int z = blockIdx.z;
    const float* in = a.in[z];
    fp16* hi = a.hi[z];
    const int base = blockIdx.x * 1024 + threadIdx.x;
#pragma unroll
    for (int jj = 0; jj < 4; jj++) {
        int i = base + jj * 256;
        float4 v = ((const float4*)in)[i];
        float f[4] = {v.x, v.y, v.z, v.w};
        union { fp16 h[4]; uint2 u; } uh;
#pragma unroll
        for (int j = 0; j < 4; j++)
            uh.h[j] = __float2half_rn(f[j]);
        ((uint2*)hi)[i] = uh.u;
    }
}

struct ConvW { const float* W[4]; fp16* hi[4]; };

__global__ void convert_wT_kernel(ConvW a)
{
    __shared__ float t[32][33];
    const int z = blockIdx.z;
    const float* W = a.W[z];
    fp16* hiT = a.hi[z];
    const int k0 = blockIdx.x * 32, n0 = blockIdx.y * 32;
    const int tx = threadIdx.x, ty = threadIdx.y;
#pragma unroll
    for (int j = 0; j < 4; j++)
        t[ty + j * 8][tx] = W[(size_t)(k0 + ty + j * 8) * D_MODEL + n0 + tx];
    __syncthreads();
#pragma unroll
    for (int j = 0; j < 4; j++) {
        float v = t[tx][ty + j * 8];
        hiT[(size_t)(n0 + ty + j * 8) * D_MODEL + k0 + tx] = __float2half_rn(v);
    }
}

// ---------------------------------------------------------------------------
// GEMM via mma.sync fp16, single-term: C = Ah*Wh^T + bias
// BK=64, 8 stages, 3-stage cp.async ring with wait_group 1 (2 stages in flight).
// mode 0: fp32 C row-major. 1: fp16 head-split hi. 2: transposed V hi.
// ---------------------------------------------------------------------------
#define BM 128
#define BN 128
#define BK 64
#define GSK 72                          // padded row stride (fp16) for 64-wide rows
#define MAT_ELEMS (128 * GSK)           // 9216 fp16 per matrix tile
#define STAGE_ELEMS (2 * MAT_ELEMS)     // A + B
#define NRING 3

struct GemmJob {
    const fp16 *Ah, *Bh;
    const float* bias;
    float* Cf;
    fp16 *Chi;
    int mode;
    float oscale;
};

__global__ void __launch_bounds__(256, 2) gemm_mma_kernel(GemmJob jb)
{
    extern __shared__ __align__(16) fp16 sm[];
    const fp16* __restrict__ Ahi = jb.Ah;
    const fp16* __restrict__ Bhi = jb.Bh;
    const float* __restrict__ bias = jb.bias;

    const int tid = threadIdx.x;
    const int lane = tid & 31, warp = tid >> 5;
    const int wm = warp >> 2, wn = warp & 3;
    const int m0 = blockIdx.y * BM, n0 = blockIdx.x * BN;

    const uint32_t s0 = (uint32_t)__cvta_generic_to_shared(sm);

    // loader: 1024 16B-chunks per matrix tile; 4 per thread per matrix.
    const uint32_t lrow = (uint32_t)(tid >> 3);
    const uint32_t lcol = (uint32_t)(tid & 7) * 8;
    const uint32_t sOffB = (lrow * GSK + lcol) * 2;
    const uint32_t gOffA = lrow * D_MODEL + lcol;
    const uint32_t gOffB = lrow * D_MODEL + lcol;

    float acc[4][4][4];
#pragma unroll
    for (int a = 0; a < 4; a++)
#pragma unroll
        for (int b = 0; b < 4; b++)
#pragma unroll
            for (int c = 0; c < 4; c++) acc[a][b][c] = 0.f;

    const uint32_t aRow = wm * 64 + (lane & 15);
    const uint32_t aCol = (lane >> 4) * 8;
    const uint32_t bRow = wn * 32 + (lane & 7) + ((lane >> 4) & 1) * 8;
    const uint32_t bCol = ((lane >> 3) & 1) * 8;

#define LOAD_STAGE(S, K0) do { \
    uint32_t sb = s0 + (uint32_t)((S) % NRING) * STAGE_ELEMS * 2; \
    _Pragma("unroll") \
    for (int i = 0; i < 4; i++) { \
        uint32_t so = sOffB + (uint32_t)(i * 32) * GSK * 2; \
        CP16(sb + so, Ahi + (uint32_t)(m0 + i * 32) * D_MODEL + gOffA + (K0)); \
        CP16(sb + MAT_ELEMS * 2 + so, \
             Bhi + (uint32_t)(n0 + i * 32) * D_MODEL + gOffB + (K0)); \
    } \
    asm volatile("cp.async.commit_group;"); \
} while (0)

    LOAD_STAGE(0, 0);
    LOAD_STAGE(1, BK);

    const int NSTAGE = D_MODEL / BK;   // 8
    for (int s = 0; s < NSTAGE; ++s) {
        if (s < NSTAGE - 1)
            asm volatile("cp.async.wait_group 1;" ::: "memory");
        else
            asm volatile("cp.async.wait_group 0;" ::: "memory");
        __syncthreads();
        if (s + 2 < NSTAGE) LOAD_STAGE(s + 2, (uint32_t)(s + 2) * BK);

        const uint32_t sb = s0 + (uint32_t)(s % NRING) * STAGE_ELEMS * 2;
        const uint32_t aBaseH = sb + (aRow * GSK + aCol) * 2;
        const uint32_t bBaseH = sb + MAT_ELEMS * 2 + (bRow * GSK + bCol) * 2;

#pragma unroll
        for (int ks = 0; ks < 4; ++ks) {
            uint32_t ah[4][4], bh[4][2];
#pragma unroll
            for (int mf = 0; mf < 4; ++mf) {
                uint32_t off = (uint32_t)(mf * 16 * GSK + ks * 16) * 2;
                LDSM4(ah[mf][0], ah[mf][1], ah[mf][2], ah[mf][3], aBaseH + off);
            }
#pragma unroll
            for (int p = 0; p < 2; ++p) {
                uint32_t off = (uint32_t)(p * 16 * GSK + ks * 16) * 2;
                LDSM4(bh[2 * p][0], bh[2 * p][1], bh[2 * p + 1][0], bh[2 * p + 1][1], bBaseH + off);
            }
#pragma unroll
            for (int mf = 0; mf < 4; ++mf)
#pragma unroll
                for (int nf = 0; nf < 4; ++nf)
                    MMA_F16(acc[mf][nf], ah[mf], bh[nf]);
        }
    }

    const int l4 = lane >> 2, l2 = (lane & 3) * 2;
#pragma unroll
    for (int mf = 0; mf < 4; ++mf) {
#pragma unroll
        for (int nf = 0; nf < 4; ++nf) {
            const int r = m0 + wm * 64 + mf * 16 + l4;
            const int c = n0 + wn * 32 + nf * 8 + l2;
            const float bx = bias[c], by = bias[c + 1];
            float v00 = acc[mf][nf][0] + bx, v01 = acc[mf][nf][1] + by;
            float v10 = acc[mf][nf][2] + bx, v11 = acc[mf][nf][3] + by;
            if (jb.mode == 0) {
                *(float2*)&jb.Cf[(size_t)r * D_MODEL + c] = make_float2(v00, v01);
                *(float2*)&jb.Cf[(size_t)(r + 8) * D_MODEL + c] = make_float2(v10, v11);
            } else {
                v00 *= jb.oscale; v01 *= jb.oscale; v10 *= jb.oscale; v11 *= jb.oscale;
                const int b = r >> 11, sx = r & (SEQ - 1);
                const int h = c >> 6, d = c & (DK - 1);
                const int bhh = b * HEADS + h;
                if (jb.mode == 1) {
                    __half2 h0 = __floats2half2_rn(v00, v01);
                    __half2 h1 = __floats2half2_rn(v10, v11);
                    size_t o0 = ((size_t)bhh * SEQ + sx) * DK + d;
                    size_t o1 = ((size_t)bhh * SEQ + sx + 8) * DK + d;
                    *(__half2*)&jb.Chi[o0] = h0;
                    *(__half2*)&jb.Chi[o1] = h1;
                } else {  // mode 2: transposed [bh][d][s]
                    size_t base = (size_t)bhh * DK * SEQ;
                    float vv[4] = {v00, v01, v10, v11};
                    int dd[4] = {d, d + 1, d, d + 1};
                    int ss[4] = {sx, sx, sx + 8, sx + 8};
#pragma unroll
                    for (int e = 0; e < 4; e++)
                        jb.Chi[base + (size_t)dd[e] * SEQ + ss[e]] = __float2half_rn(vv[e]);
                }
            }
        }
    }
}

// ---------------------------------------------------------------------------
// base-2 fast exp: e^x with y = x*log2e preformed; exp2_fast(0)==1.0 exactly.
// ---------------------------------------------------------------------------
__device__ __forceinline__ float exp2_fast(float y)
{
    float jf = y + 12582912.f;
    float t = (y - (jf - 12582912.f)) * 0.6931471805599453f;
    float p = fmaf(t, 0.041666668f, 0.16666667f);
    p = fmaf(t, p, 0.5f);
    p = fmaf(t, p, 1.0f);
    p = fmaf(t, p, 1.0f);
    int e = (__float_as_int(jf) - 0x4B400000 + 127) << 23;
    return p * __int_as_float(e);
}

// ---------------------------------------------------------------------------
// Flash attention (causal), fp16 single-term QK and PV — unchanged.
// ---------------------------------------------------------------------------
#define FSK 72
#define FTILE (64 * FSK)
#define FSTAGE (2 * FTILE)

__global__ void __launch_bounds__(128, 4) flash_mma_kernel(
    const fp16* __restrict__ Qh,
    const fp16* __restrict__ Kh, const fp16* __restrict__ Vh,
    fp16* __restrict__ Ohi)
{
    extern __shared__ __align__(16) fp16 fsm[];
    const int tid = threadIdx.x, lane = tid & 31, w = tid >> 5;
    const int qt = gridDim.x - 1 - blockIdx.x, bh = blockIdx.y;

    const uint32_t sb = (uint32_t)__cvta_generic_to_shared(fsm);
    const uint32_t sQh = sb + FSTAGE * 2;               // Q staged in buffer 1

    const size_t gQ = ((size_t)bh * SEQ + (size_t)qt * 64) * DK;
    const size_t gK = (size_t)bh * SEQ * DK;
    const size_t gV = (size_t)bh * DK * SEQ;

#define FLOADQ() do { \
    _Pragma("unroll") \
    for (int i = 0; i < 4; i++) { \
        int idx = tid + i * 128; int rr = idx >> 3; int cc = (idx & 7) * 8; \
        uint32_t so = (uint32_t)(rr * FSK + cc) * 2; \
        CP16(sQh + so, Qh + gQ + rr * DK + cc); \
    } \
} while (0)

#define FLOADKV(S, KT) do { \
    uint32_t st = sb + (uint32_t)(S) * FSTAGE * 2; \
    _Pragma("unroll") \
    for (int i = 0; i < 4; i++) { \
        int idx = tid + i * 128; int rr = idx >> 3; int cc = (idx & 7) * 8; \
        uint32_t so = (uint32_t)(rr * FSK + cc) * 2; \
        CP16(st + so,             Kh + gK + (size_t)((KT) * 64 + rr) * DK + cc); \
        CP16(st + FTILE * 2 + so, Vh + gV + (size_t)rr * SEQ + (KT) * 64 + cc); \
    } \
    asm volatile("cp.async.commit_group;"); \
} while (0)

    FLOADQ();
    FLOADKV(0, 0);

    const uint32_t aOff = (uint32_t)((w * 16 + (lane & 15)) * FSK + (lane >> 4) * 8) * 2;
    const uint32_t bRowOff = (lane & 7) + ((lane >> 4) & 1) * 8;
    const uint32_t bColOff = ((lane >> 3) & 1) * 8;

    const int l4 = lane >> 2, l2 = (lane & 3) * 2;
    const int rowBaseA = w * 16 + l4;
    float m0 = -3.0e38f, m1 = -3.0e38f, l0 = 0.f, l1 = 0.f;
    float o[8][4];
#pragma unroll
    for (int n = 0; n < 8; n++)
#pragma unroll
        for (int c = 0; c < 4; c++) o[n][c] = 0.f;

    uint32_t qhf[4][4];

    for (int kt = 0; kt <= qt; ++kt) {
        asm volatile("cp.async.wait_group 0;" ::: "memory");
        __syncthreads();

        if (kt == 0) {
#pragma unroll
            for (int kk = 0; kk < 4; ++kk) {
                uint32_t off = aOff + (uint32_t)(kk * 16) * 2;
                LDSM4(qhf[kk][0], qhf[kk][1], qhf[kk][2], qhf[kk][3], sQh + off);
            }
            __syncthreads();
            if (kt < qt) FLOADKV(1, 1);
        } else {
            if (kt < qt) FLOADKV((kt + 1) & 1, kt + 1);
        }

        const uint32_t stg = sb + (uint32_t)(kt & 1) * FSTAGE * 2;

        float s[8][4];
#pragma unroll
        for (int n = 0; n < 8; n++)
#pragma unroll
            for (int c = 0; c < 4; c++) s[n][c] = 0.f;

#pragma unroll
        for (int kk = 0; kk < 4; ++kk) {
            uint32_t khf[8][2];
#pragma unroll
            for (int p = 0; p < 4; ++p) {
                uint32_t off = (uint32_t)((p * 16 + bRowOff) * FSK + bColOff + kk * 16) * 2;
                LDSM4(khf[2 * p][0], khf[2 * p][1], khf[2 * p + 1][0], khf[2 * p + 1][1], stg + off);
            }
#pragma unroll
            for (int n = 0; n < 8; n++)
                MMA_F16(s[n], qhf[kk], khf[n]);
        }

        float r0 = -3.0e38f, r1 = -3.0e38f;
#pragma unroll
        for (int n = 0; n < 8; n++) {
            r0 = fmaxf(r0, fmaxf(s[n][0], s[n][1]));
            r1 = fmaxf(r1, fmaxf(s[n][2], s[n][3]));
        }
        r0 = fmaxf(r0, __shfl_xor_sync(0xffffffffu, r0, 1));
        r0 = fmaxf(r0, __shfl_xor_sync(0xffffffffu, r0, 2));
        r1 = fmaxf(r1, __shfl_xor_sync(0xffffffffu, r1, 1));
        r1 = fmaxf(r1, __shfl_xor_sync(0xffffffffu, r1, 2));

        float mn0 = fmaxf(m0, r0), mn1 = fmaxf(m1, r1);
        if ((mn0 > m0) | (mn1 > m1)) {
            float c0 = exp2_fast(fmaxf((m0 - mn0) * LOG2E, -126.f));
            float c1 = exp2_fast(fmaxf((m1 - mn1) * LOG2E, -126.f));
            l0 *= c0; l1 *= c1;
#pragma unroll
            for (int n = 0; n < 8; n++) {
                o[n][0] *= c0; o[n][1] *= c0;
                o[n][2] *= c1; o[n][3] *= c1;
            }
            m0 = mn0; m1 = mn1;
        }
        const float ym0 = m0 * LOG2E, ym1 = m1 * LOG2E;

        const bool diag = (kt == qt);
        float ls0 = 0.f, ls1 = 0.f;
#pragma unroll
        for (int n = 0; n < 8; n++) {
            float p0 = exp2_fast(fmaf(s[n][0], LOG2E, -ym0));
            float p1 = exp2_fast(fmaf(s[n][1], LOG2E, -ym0));
            float p2 = exp2_fast(fmaf(s[n][2], LOG2E, -ym1));
            float p3 = exp2_fast(fmaf(s[n][3], LOG2E, -ym1));
            if (diag) {
                int cb = n * 8 + l2;
                if (cb > rowBaseA) p0 = 0.f;
                if (cb + 1 > rowBaseA) p1 = 0.f;
                if (cb > rowBaseA + 8) p2 = 0.f;
                if (cb + 1 > rowBaseA + 8) p3 = 0.f;
            }
            s[n][0] = p0; s[n][1] = p1; s[n][2] = p2; s[n][3] = p3;
            ls0 += p0 + p1; ls1 += p2 + p3;
        }
        l0 += ls0;
        l1 += ls1;

        uint32_t aPh[4][4];
#pragma unroll
        for (int kk = 0; kk < 4; ++kk) {
            const int n0i = 2 * kk, n1i = 2 * kk + 1;
            __half2 h;
            h = __floats2half2_rn(s[n0i][0], s[n0i][1]); aPh[kk][0] = *(uint32_t*)&h;
            h = __floats2half2_rn(s[n0i][2], s[n0i][3]); aPh[kk][1] = *(uint32_t*)&h;
            h = __floats2half2_rn(s[n1i][0], s[n1i][1]); aPh[kk][2] = *(uint32_t*)&h;
            h = __floats2half2_rn(s[n1i][2], s[n1i][3]); aPh[kk][3] = *(uint32_t*)&h;
        }

#pragma unroll
        for (int kk = 0; kk < 4; ++kk) {
            uint32_t vhf[8][2];
#pragma unroll
            for (int p = 0; p < 4; ++p) {
                uint32_t off = (uint32_t)((p * 16 + bRowOff) * FSK + bColOff + kk * 16) * 2;
                LDSM4(vhf[2 * p][0], vhf[2 * p][1], vhf[2 * p + 1][0], vhf[2 * p + 1][1],
                      stg + FTILE * 2 + off);
            }
#pragma unroll
            for (int n = 0; n < 8; n++)
                MMA_F16(o[n], aPh[kk], vhf[n]);
        }
    }

    l0 += __shfl_xor_sync(0xffffffffu, l0, 1);
    l0 += __shfl_xor_sync(0xffffffffu, l0, 2);
    l1 += __shfl_xor_sync(0xffffffffu, l1, 1);
    l1 += __shfl_xor_sync(0xffffffffu, l1, 2);
    const float inv0 = 1.f / l0, inv1 = 1.f / l1;

    const int b = bh >> 4, hh = bh & 15;
    const int grow = qt * 64 + rowBaseA;
    const size_t rbase0 = ((size_t)b * SEQ + grow) * D_MODEL + hh * DK;
    const size_t rbase1 = rbase0 + (size_t)8 * D_MODEL;
#pragma unroll
    for (int n = 0; n < 8; n++) {
        const int d = n * 8 + l2;
        __half2 h0 = __floats2half2_rn(o[n][0] * inv0, o[n][1] * inv0);
        __half2 h1 = __floats2half2_rn(o[n][2] * inv1, o[n][3] * inv1);
        *(__half2*)&Ohi[rbase0 + d] = h0;
        *(__half2*)&Ohi[rbase1 + d] = h1;
    }
}

// ---------------------------------------------------------------------------
extern "C" void kernel_launch(void* const* d_in, const int* in_sizes, int n_in,
                              void* d_out, int out_size)
{
    const float* query = (const float*)d_in[0];
    const float* key   = (const float*)d_in[1];
    const float* value = (const float*)d_in[2];
    // d_in[3] = mask (causal handled analytically)
    const float* Wq = (const float*)d_in[4];
    const float* bq = (const float*)d_in[5];
    const float* Wk = (const float*)d_in[6];
    const float* bk = (const float*)d_in[7];
    const float* Wv = (const float*)d_in[8];
    const float* bv = (const float*)d_in[9];
    const float* Wo = (const float*)d_in[10];
    const float* bo = (const float*)d_in[11];
    float* out = (float*)d_out;

    fp16 *ahi, *whi, *qhi, *khi, *vhi;
    cudaGetSymbolAddress((void**)&ahi, g_ahi);
    cudaGetSymbolAddress((void**)&whi, g_whi);
    cudaGetSymbolAddress((void**)&qhi, g_qhi);
    cudaGetSymbolAddress((void**)&khi, g_khi);
    cudaGetSymbolAddress((void**)&vhi, g_vhi);

    const size_t ASTRIDE = (size_t)M_ROWS * D_MODEL;
    const size_t WSTRIDE = (size_t)D_MODEL * D_MODEL;

    const int gemm_smem = NRING * STAGE_ELEMS * 2;  // 110592 B (x2 CTAs = 221KB/SM)
    cudaFuncSetAttribute(gemm_mma_kernel,
                         cudaFuncAttributeMaxDynamicSharedMemorySize, gemm_smem);
    const int flash_smem = 2 * FSTAGE * 2;          // 36864 B
    cudaFuncSetAttribute(flash_mma_kernel,
                         cudaFuncAttributeMaxDynamicSharedMemorySize, flash_smem);

    // 1. convert activations (hi only)
    ConvA ca;
    ca.in[0] = query; ca.in[1] = key; ca.in[2] = value;
    for (int i = 0; i < 3; i++) ca.hi[i] = ahi + i * ASTRIDE;
    convert_act_kernel<<<dim3(M_ROWS * D_MODEL / 4096, 1, 3), 256>>>(ca);

    // 2. convert + transpose weights (hi only)
    ConvW cw;
    cw.W[0] = Wq; cw.W[1] = Wk; cw.W[2] = Wv; cw.W[3] = Wo;
    for (int i = 0; i < 4; i++) cw.hi[i] = whi + i * WSTRIDE;
    convert_wT_kernel<<<dim3(32, 32, 4), dim3(32, 8)>>>(cw);

    // 3-5. QKV projections (single-term, BK=64, 3-stage ring)
    dim3 gg(D_MODEL / BN, M_ROWS / BM);
    GemmJob jq = { ahi + 0 * ASTRIDE, whi + 0 * WSTRIDE, bq, nullptr, qhi, 1, 0.125f };
    gemm_mma_kernel<<<gg, 256, gemm_smem>>>(jq);
    GemmJob jk = { ahi + 1 * ASTRIDE, whi + 1 * WSTRIDE, bk, nullptr, khi, 1, 1.0f };
    gemm_mma_kernel<<<gg, 256, gemm_smem>>>(jk);
    GemmJob jv = { ahi + 2 * ASTRIDE, whi + 2 * WSTRIDE, bv, nullptr, vhi, 2, 1.0f };
    gemm_mma_kernel<<<gg, 256, gemm_smem>>>(jv);

    // 6. flash attention — writes O (hi) into activation set 0
    flash_mma_kernel<<<dim3(SEQ / 64, BH), 128, flash_smem>>>(
        qhi, khi, vhi, ahi);

    // 7. output projection — fp32 out
    GemmJob jo = { ahi, whi + 3 * WSTRIDE, bo, out, nullptr, 0, 1.0f };
    gemm_mma_kernel<<<gg, 256, gemm_smem>>>(jo);
}

// round 17
// speedup vs baseline: 1.0588x; 1.0588x over previous
#include <cuda_runtime.h>
#include <cuda_fp16.h>
#include <stdint.h>
#include <math.h>

#define D_MODEL 1024
#define HEADS 16
#define DK 64
#define BATCH 2
#define SEQ 2048
#define M_ROWS (BATCH * SEQ)   // 4096
#define BH (BATCH * HEADS)     // 32
#define LOG2E 1.4426950408889634f

typedef __half fp16;

// ---------------- scratch (static device globals; no allocation) -------------
__device__ fp16 g_ahi[(size_t)3 * M_ROWS * D_MODEL];   // activation sets (hi only)
__device__ fp16 g_whi[(size_t)4 * D_MODEL * D_MODEL];  // W^T hi only [N][K]
__device__ fp16 g_qhi[(size_t)BH * SEQ * DK];          // [bh][s][d], pre-scaled 0.125
__device__ fp16 g_khi[(size_t)BH * SEQ * DK];
__device__ fp16 g_vhi[(size_t)BH * DK * SEQ];          // transposed [bh][d][s]

// ---------------------------------------------------------------------------
// MMA building blocks (mma.sync path — tcgen05 unavailable: harness PTX
// targets sm_103 without the 'a' feature suffix). fp16 inputs, fp32 accum.
// ---------------------------------------------------------------------------
#define LDSM4(R0, R1, R2, R3, ADDR) \
    asm volatile("ldmatrix.sync.aligned.m8n8.x4.shared.b16 {%0,%1,%2,%3}, [%4];" \
        : "=r"(R0), "=r"(R1), "=r"(R2), "=r"(R3) : "r"(ADDR))

#define MMA_F16(D, A, B) \
    asm volatile("mma.sync.aligned.m16n8k16.row.col.f32.f16.f16.f32 " \
        "{%0,%1,%2,%3}, {%4,%5,%6,%7}, {%8,%9}, {%0,%1,%2,%3};" \
        : "+f"(D[0]), "+f"(D[1]), "+f"(D[2]), "+f"(D[3]) \
        : "r"(A[0]), "r"(A[1]), "r"(A[2]), "r"(A[3]), "r"(B[0]), "r"(B[1]))

#define CP16(DST, SRC) \
    asm volatile("cp.async.cg.shared.global [%0], [%1], 16;" :: "r"(DST), "l"(SRC))

// ---------------------------------------------------------------------------
// merged converts (grid.z selects tensor) — hi plane only
// ---------------------------------------------------------------------------
struct ConvA { const float* in[3]; fp16* hi[3]; };

__global__ void __launch_bounds__(256) convert_act_kernel(ConvA a)
{
    const int z = blockIdx.z;
    const float* in = a.in[z];
    fp16* hi = a.hi[z];
    const int base = blockIdx.x * 1024 + threadIdx.x;
#pragma unroll
    for (int jj = 0; jj < 4; jj++) {
        int i = base + jj * 256;
        float4 v = ((const float4*)in)[i];
        float f[4] = {v.x, v.y, v.z, v.w};
        union { fp16 h[4]; uint2 u; } uh;
#pragma unroll
        for (int j = 0; j < 4; j++)
            uh.h[j] = __float2half_rn(f[j]);
        ((uint2*)hi)[i] = uh.u;
    }
}

struct ConvW { const float* W[4]; fp16* hi[4]; };

__global__ void convert_wT_kernel(ConvW a)
{
    __shared__ float t[32][33];
    const int z = blockIdx.z;
    const float* W = a.W[z];
    fp16* hiT = a.hi[z];
    const int k0 = blockIdx.x * 32, n0 = blockIdx.y * 32;
    const int tx = threadIdx.x, ty = threadIdx.y;
#pragma unroll
    for (int j = 0; j < 4; j++)
        t[ty + j * 8][tx] = W[(size_t)(k0 + ty + j * 8) * D_MODEL + n0 + tx];
    __syncthreads();
#pragma unroll
    for (int j = 0; j < 4; j++) {
        float v = t[tx][ty + j * 8];
        hiT[(size_t)(n0 + ty + j * 8) * D_MODEL + k0 + tx] = __float2half_rn(v);
    }
}

// ---------------------------------------------------------------------------
// GEMM via mma.sync fp16, single-term: C = Ah*Wh^T + bias
// BK=64, 8 stages, 3-stage cp.async ring (wait_group 1). grid.z = job index.
// mode 0: fp32 C row-major. 1: fp16 head-split hi. 2: transposed V hi.
// ---------------------------------------------------------------------------
#define BM 128
#define BN 128
#define BK 64
#define GSK 72                          // padded row stride (fp16) for 64-wide rows
#define MAT_ELEMS (128 * GSK)           // 9216 fp16 per matrix tile
#define STAGE_ELEMS (2 * MAT_ELEMS)     // A + B
#define NRING 3

struct GemmJob {
    const fp16 *Ah, *Bh;
    const float* bias;
    float* Cf;
    fp16 *Chi;
    int mode;
    float oscale;
};
struct GemmArgs { GemmJob job[3]; };

__global__ void __launch_bounds__(256, 2) gemm_mma_kernel(GemmArgs args)
{
    extern __shared__ __align__(16) fp16 sm[];
    const GemmJob jb = args.job[blockIdx.z];
    const fp16* __restrict__ Ahi = jb.Ah;
    const fp16* __restrict__ Bhi = jb.Bh;
    const float* __restrict__ bias = jb.bias;

    const int tid = threadIdx.x;
    const int lane = tid & 31, warp = tid >> 5;
    const int wm = warp >> 2, wn = warp & 3;
    const int m0 = blockIdx.y * BM, n0 = blockIdx.x * BN;

    const uint32_t s0 = (uint32_t)__cvta_generic_to_shared(sm);

    const uint32_t lrow = (uint32_t)(tid >> 3);
    const uint32_t lcol = (uint32_t)(tid & 7) * 8;
    const uint32_t sOffB = (lrow * GSK + lcol) * 2;
    const uint32_t gOffA = lrow * D_MODEL + lcol;
    const uint32_t gOffB = lrow * D_MODEL + lcol;

    float acc[4][4][4];
#pragma unroll
    for (int a = 0; a < 4; a++)
#pragma unroll
        for (int b = 0; b < 4; b++)
#pragma unroll
            for (int c = 0; c < 4; c++) acc[a][b][c] = 0.f;

    const uint32_t aRow = wm * 64 + (lane & 15);
    const uint32_t aCol = (lane >> 4) * 8;
    const uint32_t bRow = wn * 32 + (lane & 7) + ((lane >> 4) & 1) * 8;
    const uint32_t bCol = ((lane >> 3) & 1) * 8;

#define LOAD_STAGE(S, K0) do { \
    uint32_t sb = s0 + (uint32_t)((S) % NRING) * STAGE_ELEMS * 2; \
    _Pragma("unroll") \
    for (int i = 0; i < 4; i++) { \
        uint32_t so = sOffB + (uint32_t)(i * 32) * GSK * 2; \
        CP16(sb + so, Ahi + (uint32_t)(m0 + i * 32) * D_MODEL + gOffA + (K0)); \
        CP16(sb + MAT_ELEMS * 2 + so, \
             Bhi + (uint32_t)(n0 + i * 32) * D_MODEL + gOffB + (K0)); \
    } \
    asm volatile("cp.async.commit_group;"); \
} while (0)

    LOAD_STAGE(0, 0);
    LOAD_STAGE(1, BK);

    const int NSTAGE = D_MODEL / BK;   // 8
    for (int s = 0; s < NSTAGE; ++s) {
        if (s < NSTAGE - 1)
            asm volatile("cp.async.wait_group 1;" ::: "memory");
        else
            asm volatile("cp.async.wait_group 0;" ::: "memory");
        __syncthreads();
        if (s + 2 < NSTAGE) LOAD_STAGE(s + 2, (uint32_t)(s + 2) * BK);

        const uint32_t sb = s0 + (uint32_t)(s % NRING) * STAGE_ELEMS * 2;
        const uint32_t aBaseH = sb + (aRow * GSK + aCol) * 2;
        const uint32_t bBaseH = sb + MAT_ELEMS * 2 + (bRow * GSK + bCol) * 2;

#pragma unroll
        for (int ks = 0; ks < 4; ++ks) {
            uint32_t ah[4][4], bh[4][2];
#pragma unroll
            for (int mf = 0; mf < 4; ++mf) {
                uint32_t off = (uint32_t)(mf * 16 * GSK + ks * 16) * 2;
                LDSM4(ah[mf][0], ah[mf][1], ah[mf][2], ah[mf][3], aBaseH + off);
            }
#pragma unroll
            for (int p = 0; p < 2; ++p) {
                uint32_t off = (uint32_t)(p * 16 * GSK + ks * 16) * 2;
                LDSM4(bh[2 * p][0], bh[2 * p][1], bh[2 * p + 1][0], bh[2 * p + 1][1], bBaseH + off);
            }
#pragma unroll
            for (int mf = 0; mf < 4; ++mf)
#pragma unroll
                for (int nf = 0; nf < 4; ++nf)
                    MMA_F16(acc[mf][nf], ah[mf], bh[nf]);
        }
    }

    const int l4 = lane >> 2, l2 = (lane & 3) * 2;
#pragma unroll
    for (int mf = 0; mf < 4; ++mf) {
#pragma unroll
        for (int nf = 0; nf < 4; ++nf) {
            const int r = m0 + wm * 64 + mf * 16 + l4;
            const int c = n0 + wn * 32 + nf * 8 + l2;
            const float bx = bias[c], by = bias[c + 1];
            float v00 = acc[mf][nf][0] + bx, v01 = acc[mf][nf][1] + by;
            float v10 = acc[mf][nf][2] + bx, v11 = acc[mf][nf][3] + by;
            if (jb.mode == 0) {
                *(float2*)&jb.Cf[(size_t)r * D_MODEL + c] = make_float2(v00, v01);
                *(float2*)&jb.Cf[(size_t)(r + 8) * D_MODEL + c] = make_float2(v10, v11);
            } else {
                v00 *= jb.oscale; v01 *= jb.oscale; v10 *= jb.oscale; v11 *= jb.oscale;
                const int b = r >> 11, sx = r & (SEQ - 1);
                const int h = c >> 6, d = c & (DK - 1);
                const int bhh = b * HEADS + h;
                if (jb.mode == 1) {
                    __half2 h0 = __floats2half2_rn(v00, v01);
                    __half2 h1 = __floats2half2_rn(v10, v11);
                    size_t o0 = ((size_t)bhh * SEQ + sx) * DK + d;
                    size_t o1 = ((size_t)bhh * SEQ + sx + 8) * DK + d;
                    *(__half2*)&jb.Chi[o0] = h0;
                    *(__half2*)&jb.Chi[o1] = h1;
                } else {  // mode 2: transposed [bh][d][s]
                    size_t base = (size_t)bhh * DK * SEQ;
                    float vv[4] = {v00, v01, v10, v11};
                    int dd[4] = {d, d + 1, d, d + 1};
                    int ss[4] = {sx, sx, sx + 8, sx + 8};
#pragma unroll
                    for (int e = 0; e < 4; e++)
                        jb.Chi[base + (size_t)dd[e] * SEQ + ss[e]] = __float2half_rn(vv[e]);
                }
            }
        }
    }
}

// ---------------------------------------------------------------------------
// base-2 fast exp: e^x with y = x*log2e preformed; exp2_fast(0)==1.0 exactly.
// ---------------------------------------------------------------------------
__device__ __forceinline__ float exp2_fast(float y)
{
    float jf = y + 12582912.f;
    float t = (y - (jf - 12582912.f)) * 0.6931471805599453f;
    float p = fmaf(t, 0.041666668f, 0.16666667f);
    p = fmaf(t, p, 0.5f);
    p = fmaf(t, p, 1.0f);
    p = fmaf(t, p, 1.0f);
    int e = (__float_as_int(jf) - 0x4B400000 + 127) << 23;
    return p * __int_as_float(e);
}

// ---------------------------------------------------------------------------
// Flash attention (causal), fp16 single-term QK and PV — unchanged.
// ---------------------------------------------------------------------------
#define FSK 72
#define FTILE (64 * FSK)
#define FSTAGE (2 * FTILE)

__global__ void __launch_bounds__(128, 4) flash_mma_kernel(
    const fp16* __restrict__ Qh,
    const fp16* __restrict__ Kh, const fp16* __restrict__ Vh,
    fp16* __restrict__ Ohi)
{
    extern __shared__ __align__(16) fp16 fsm[];
    const int tid = threadIdx.x, lane = tid & 31, w = tid >> 5;
    const int qt = gridDim.x - 1 - blockIdx.x, bh = blockIdx.y;

    const uint32_t sb = (uint32_t)__cvta_generic_to_shared(fsm);
    const uint32_t sQh = sb + FSTAGE * 2;               // Q staged in buffer 1

    const size_t gQ = ((size_t)bh * SEQ + (size_t)qt * 64) * DK;
    const size_t gK = (size_t)bh * SEQ * DK;
    const size_t gV = (size_t)bh * DK * SEQ;

#define FLOADQ() do { \
    _Pragma("unroll") \
    for (int i = 0; i < 4; i++) { \
        int idx = tid + i * 128; int rr = idx >> 3; int cc = (idx & 7) * 8; \
        uint32_t so = (uint32_t)(rr * FSK + cc) * 2; \
        CP16(sQh + so, Qh + gQ + rr * DK + cc); \
    } \
} while (0)

#define FLOADKV(S, KT) do { \
    uint32_t st = sb + (uint32_t)(S) * FSTAGE * 2; \
    _Pragma("unroll") \
    for (int i = 0; i < 4; i++) { \
        int idx = tid + i * 128; int rr = idx >> 3; int cc = (idx & 7) * 8; \
        uint32_t so = (uint32_t)(rr * FSK + cc) * 2; \
        CP16(st + so,             Kh + gK + (size_t)((KT) * 64 + rr) * DK + cc); \
        CP16(st + FTILE * 2 + so, Vh + gV + (size_t)rr * SEQ + (KT) * 64 + cc); \
    } \
    asm volatile("cp.async.commit_group;"); \
} while (0)

    FLOADQ();
    FLOADKV(0, 0);

    const uint32_t aOff = (uint32_t)((w * 16 + (lane & 15)) * FSK + (lane >> 4) * 8) * 2;
    const uint32_t bRowOff = (lane & 7) + ((lane >> 4) & 1) * 8;
    const uint32_t bColOff = ((lane >> 3) & 1) * 8;

    const int l4 = lane >> 2, l2 = (lane & 3) * 2;
    const int rowBaseA = w * 16 + l4;
    float m0 = -3.0e38f, m1 = -3.0e38f, l0 = 0.f, l1 = 0.f;
    float o[8][4];
#pragma unroll
    for (int n = 0; n < 8; n++)
#pragma unroll
        for (int c = 0; c < 4; c++) o[n][c] = 0.f;

    uint32_t qhf[4][4];

    for (int kt = 0; kt <= qt; ++kt) {
        asm volatile("cp.async.wait_group 0;" ::: "memory");
        __syncthreads();

        if (kt == 0) {
#pragma unroll
            for (int kk = 0; kk < 4; ++kk) {
                uint32_t off = aOff + (uint32_t)(kk * 16) * 2;
                LDSM4(qhf[kk][0], qhf[kk][1], qhf[kk][2], qhf[kk][3], sQh + off);
            }
            __syncthreads();
            if (kt < qt) FLOADKV(1, 1);
        } else {
            if (kt < qt) FLOADKV((kt + 1) & 1, kt + 1);
        }

        const uint32_t stg = sb + (uint32_t)(kt & 1) * FSTAGE * 2;

        float s[8][4];
#pragma unroll
        for (int n = 0; n < 8; n++)
#pragma unroll
            for (int c = 0; c < 4; c++) s[n][c] = 0.f;

#pragma unroll
        for (int kk = 0; kk < 4; ++kk) {
            uint32_t khf[8][2];
#pragma unroll
            for (int p = 0; p < 4; ++p) {
                uint32_t off = (uint32_t)((p * 16 + bRowOff) * FSK + bColOff + kk * 16) * 2;
                LDSM4(khf[2 * p][0], khf[2 * p][1], khf[2 * p + 1][0], khf[2 * p + 1][1], stg + off);
            }
#pragma unroll
            for (int n = 0; n < 8; n++)
                MMA_F16(s[n], qhf[kk], khf[n]);
        }

        float r0 = -3.0e38f, r1 = -3.0e38f;
#pragma unroll
        for (int n = 0; n < 8; n++) {
            r0 = fmaxf(r0, fmaxf(s[n][0], s[n][1]));
            r1 = fmaxf(r1, fmaxf(s[n][2], s[n][3]));
        }
        r0 = fmaxf(r0, __shfl_xor_sync(0xffffffffu, r0, 1));
        r0 = fmaxf(r0, __shfl_xor_sync(0xffffffffu, r0, 2));
        r1 = fmaxf(r1, __shfl_xor_sync(0xffffffffu, r1, 1));
        r1 = fmaxf(r1, __shfl_xor_sync(0xffffffffu, r1, 2));

        float mn0 = fmaxf(m0, r0), mn1 = fmaxf(m1, r1);
        if ((mn0 > m0) | (mn1 > m1)) {
            float c0 = exp2_fast(fmaxf((m0 - mn0) * LOG2E, -126.f));
            float c1 = exp2_fast(fmaxf((m1 - mn1) * LOG2E, -126.f));
            l0 *= c0; l1 *= c1;
#pragma unroll
            for (int n = 0; n < 8; n++) {
                o[n][0] *= c0; o[n][1] *= c0;
                o[n][2] *= c1; o[n][3] *= c1;
            }
            m0 = mn0; m1 = mn1;
        }
        const float ym0 = m0 * LOG2E, ym1 = m1 * LOG2E;

        const bool diag = (kt == qt);
        float ls0 = 0.f, ls1 = 0.f;
#pragma unroll
        for (int n = 0; n < 8; n++) {
            float p0 = exp2_fast(fmaf(s[n][0], LOG2E, -ym0));
            float p1 = exp2_fast(fmaf(s[n][1], LOG2E, -ym0));
            float p2 = exp2_fast(fmaf(s[n][2], LOG2E, -ym1));
            float p3 = exp2_fast(fmaf(s[n][3], LOG2E, -ym1));
            if (diag) {
                int cb = n * 8 + l2;
                if (cb > rowBaseA) p0 = 0.f;
                if (cb + 1 > rowBaseA) p1 = 0.f;
                if (cb > rowBaseA + 8) p2 = 0.f;
                if (cb + 1 > rowBaseA + 8) p3 = 0.f;
            }
            s[n][0] = p0; s[n][1] = p1; s[n][2] = p2; s[n][3] = p3;
            ls0 += p0 + p1; ls1 += p2 + p3;
        }
        l0 += ls0;
        l1 += ls1;

        uint32_t aPh[4][4];
#pragma unroll
        for (int kk = 0; kk < 4; ++kk) {
            const int n0i = 2 * kk, n1i = 2 * kk + 1;
            __half2 h;
            h = __floats2half2_rn(s[n0i][0], s[n0i][1]); aPh[kk][0] = *(uint32_t*)&h;
            h = __floats2half2_rn(s[n0i][2], s[n0i][3]); aPh[kk][1] = *(uint32_t*)&h;
            h = __floats2half2_rn(s[n1i][0], s[n1i][1]); aPh[kk][2] = *(uint32_t*)&h;
            h = __floats2half2_rn(s[n1i][2], s[n1i][3]); aPh[kk][3] = *(uint32_t*)&h;
        }

#pragma unroll
        for (int kk = 0; kk < 4; ++kk) {
            uint32_t vhf[8][2];
#pragma unroll
            for (int p = 0; p < 4; ++p) {
                uint32_t off = (uint32_t)((p * 16 + bRowOff) * FSK + bColOff + kk * 16) * 2;
                LDSM4(vhf[2 * p][0], vhf[2 * p][1], vhf[2 * p + 1][0], vhf[2 * p + 1][1],
                      stg + FTILE * 2 + off);
            }
#pragma unroll
            for (int n = 0; n < 8; n++)
                MMA_F16(o[n], aPh[kk], vhf[n]);
        }
    }

    l0 += __shfl_xor_sync(0xffffffffu, l0, 1);
    l0 += __shfl_xor_sync(0xffffffffu, l0, 2);
    l1 += __shfl_xor_sync(0xffffffffu, l1, 1);
    l1 += __shfl_xor_sync(0xffffffffu, l1, 2);
    const float inv0 = 1.f / l0, inv1 = 1.f / l1;

    const int b = bh >> 4, hh = bh & 15;
    const int grow = qt * 64 + rowBaseA;
    const size_t rbase0 = ((size_t)b * SEQ + grow) * D_MODEL + hh * DK;
    const size_t rbase1 = rbase0 + (size_t)8 * D_MODEL;
#pragma unroll
    for (int n = 0; n < 8; n++) {
        const int d = n * 8 + l2;
        __half2 h0 = __floats2half2_rn(o[n][0] * inv0, o[n][1] * inv0);
        __half2 h1 = __floats2half2_rn(o[n][2] * inv1, o[n][3] * inv1);
        *(__half2*)&Ohi[rbase0 + d] = h0;
        *(__half2*)&Ohi[rbase1 + d] = h1;
    }
}

// ---------------------------------------------------------------------------
extern "C" void kernel_launch(void* const* d_in, const int* in_sizes, int n_in,
                              void* d_out, int out_size)
{
    const float* query = (const float*)d_in[0];
    const float* key   = (const float*)d_in[1];
    const float* value = (const float*)d_in[2];
    // d_in[3] = mask (causal handled analytically)
    const float* Wq = (const float*)d_in[4];
    const float* bq = (const float*)d_in[5];
    const float* Wk = (const float*)d_in[6];
    const float* bk = (const float*)d_in[7];
    const float* Wv = (const float*)d_in[8];
    const float* bv = (const float*)d_in[9];
    const float* Wo = (const float*)d_in[10];
    const float* bo = (const float*)d_in[11];
    float* out = (float*)d_out;

    fp16 *ahi, *whi, *qhi, *khi, *vhi;
    cudaGetSymbolAddress((void**)&ahi, g_ahi);
    cudaGetSymbolAddress((void**)&whi, g_whi);
    cudaGetSymbolAddress((void**)&qhi, g_qhi);
    cudaGetSymbolAddress((void**)&khi, g_khi);
    cudaGetSymbolAddress((void**)&vhi, g_vhi);

    const size_t ASTRIDE = (size_t)M_ROWS * D_MODEL;
    const size_t WSTRIDE = (size_t)D_MODEL * D_MODEL;

    const int gemm_smem = NRING * STAGE_ELEMS * 2;  // 110592 B (x2 CTAs = 221KB/SM)
    cudaFuncSetAttribute(gemm_mma_kernel,
                         cudaFuncAttributeMaxDynamicSharedMemorySize, gemm_smem);
    const int flash_smem = 2 * FSTAGE * 2;          // 36864 B
    cudaFuncSetAttribute(flash_mma_kernel,
                         cudaFuncAttributeMaxDynamicSharedMemorySize, flash_smem);

    // 1. convert activations (hi only)
    ConvA ca;
    ca.in[0] = query; ca.in[1] = key; ca.in[2] = value;
    for (int i = 0; i < 3; i++) ca.hi[i] = ahi + i * ASTRIDE;
    convert_act_kernel<<<dim3(M_ROWS * D_MODEL / 4096, 1, 3), 256>>>(ca);

    // 2. convert + transpose weights (hi only)
    ConvW cw;
    cw.W[0] = Wq; cw.W[1] = Wk; cw.W[2] = Wv; cw.W[3] = Wo;
    for (int i = 0; i < 4; i++) cw.hi[i] = whi + i * WSTRIDE;
    convert_wT_kernel<<<dim3(32, 32, 4), dim3(32, 8)>>>(cw);

    // 3. QKV projections — one launch, grid.z = 3 (tail backfill between jobs)
    GemmArgs gq;
    gq.job[0] = { ahi + 0 * ASTRIDE, whi + 0 * WSTRIDE, bq, nullptr, qhi, 1, 0.125f };
    gq.job[1] = { ahi + 1 * ASTRIDE, whi + 1 * WSTRIDE, bk, nullptr, khi, 1, 1.0f };
    gq.job[2] = { ahi + 2 * ASTRIDE, whi + 2 * WSTRIDE, bv, nullptr, vhi, 2, 1.0f };
    gemm_mma_kernel<<<dim3(D_MODEL / BN, M_ROWS / BM, 3), 256, gemm_smem>>>(gq);

    // 4. flash attention — writes O (hi) into activation set 0
    flash_mma_kernel<<<dim3(SEQ / 64, BH), 128, flash_smem>>>(
        qhi, khi, vhi, ahi);

    // 5. output projection — fp32 out
    GemmArgs go;
    go.job[0] = { ahi, whi + 3 * WSTRIDE, bo, out, nullptr, 0, 1.0f };
    go.job[1] = go.job[0];
    go.job[2] = go.job[0];
    gemm_mma_kernel<<<dim3(D_MODEL / BN, M_ROWS / BM, 1), 256, gemm_smem>>>(go);
}